// round 1
// baseline (speedup 1.0000x reference)
#include <cuda_runtime.h>
#include <cuda_bf16.h>
#include <float.h>

#define NUM_CLASSES 16
#define N_BOX 2048
#define MAXC 512            // max candidates per (image, class); expected ~122
#define NWORD (MAXC / 64)   // 8 suppression-mask words per row
#define TPB 256
#define MAX_PER_CLASS 100
#define MAX_DET 100
#define NCAND (NUM_CLASSES * MAX_PER_CLASS)  // 1600
#define PAD2 2048
#define SCORE_TH 0.05f
#define IOU_TH 0.5f

// Scratch (B=4 max): per-class top-100 candidates
__device__ float  g_cand_score[4 * NCAND];
__device__ float4 g_cand_box[4 * NCAND];

// strict total order: higher score first; tie -> lower original index first
__device__ __forceinline__ bool precedes(float sa, int ia, float sb, int ib) {
    return (sa > sb) || (sa == sb && ia < ib);
}

__global__ void __launch_bounds__(TPB) nms_per_class_kernel(const float* __restrict__ pred) {
    const int task = blockIdx.x;
    const int b = task / NUM_CLASSES;
    const int c = task % NUM_CLASSES;
    const int tid = threadIdx.x;

    __shared__ float s_score[MAXC];
    __shared__ int   s_idx[MAXC];
    __shared__ float4 s_box[MAXC];
    __shared__ unsigned long long s_mask[MAXC][NWORD];  // 32 KB
    __shared__ int s_cnt;
    __shared__ int s_keep[MAX_PER_CLASS];
    __shared__ int s_nkeep;

    if (tid == 0) s_cnt = 0;
    __syncthreads();

    // --- filter: class == c && score > TH ---
    const float* base = pred + (size_t)b * N_BOX * 6;
    const float fc = (float)c;
    for (int n = tid; n < N_BOX; n += TPB) {
        const float* p = base + n * 6;
        float cls = p[4];
        float sc  = p[5];
        if (cls == fc && sc > SCORE_TH) {
            int pos = atomicAdd(&s_cnt, 1);
            if (pos < MAXC) {
                s_score[pos] = sc;
                s_idx[pos]   = n;
            }
        }
    }
    __syncthreads();
    const int M = min(s_cnt, MAXC);

    // pad for bitonic sort
    for (int i = tid; i < MAXC; i += TPB) {
        if (i >= M) { s_score[i] = -FLT_MAX; s_idx[i] = 0x3fffffff; }
    }
    __syncthreads();

    // --- bitonic sort 512 elems: (score desc, idx asc) ---
    for (int k = 2; k <= MAXC; k <<= 1) {
        for (int j = k >> 1; j > 0; j >>= 1) {
            for (int i = tid; i < MAXC; i += TPB) {
                int ixj = i ^ j;
                if (ixj > i) {
                    float sa = s_score[i],   sb = s_score[ixj];
                    int   ia = s_idx[i],     ib = s_idx[ixj];
                    bool swapc = ((i & k) == 0) ? precedes(sb, ib, sa, ia)
                                                : precedes(sa, ia, sb, ib);
                    if (swapc) {
                        s_score[i] = sb; s_score[ixj] = sa;
                        s_idx[i]   = ib; s_idx[ixj]   = ia;
                    }
                }
            }
            __syncthreads();
        }
    }

    // gather boxes in sorted order (original xyxy)
    for (int i = tid; i < M; i += TPB) {
        const float* p = base + s_idx[i] * 6;
        s_box[i] = make_float4(p[0], p[1], p[2], p[3]);
    }
    __syncthreads();

    // --- suppression bitmask: mask[i] bit j set iff j>i && IoU(i,j) > 0.5 ---
    for (int i = tid; i < M; i += TPB) {
        float4 bi = s_box[i];
        float areai = (bi.z - bi.x) * (bi.w - bi.y);
        for (int w = 0; w < NWORD; ++w) {
            unsigned long long bits = 0ULL;
            int j0 = w * 64;
            int jend = min(j0 + 64, M);
            for (int j = (j0 > i + 1 ? j0 : i + 1); j < jend; ++j) {
                float4 bj = s_box[j];
                float iw = fminf(bi.z, bj.z) - fmaxf(bi.x, bj.x);
                float ih = fminf(bi.w, bj.w) - fmaxf(bi.y, bj.y);
                iw = fmaxf(iw, 0.0f);
                ih = fmaxf(ih, 0.0f);
                float inter = ih * iw;
                if (inter > 0.0f) {
                    float areaj = (bj.z - bj.x) * (bj.w - bj.y);
                    float uni = areai + areaj - inter;
                    if (inter / fmaxf(uni, 1e-8f) > IOU_TH)
                        bits |= (1ULL << (j - j0));
                }
            }
            s_mask[i][w] = bits;
        }
    }
    __syncthreads();

    // --- greedy sweep (cheap serial: ~M * NWORD word ops) ---
    if (tid == 0) {
        unsigned long long remv[NWORD];
        #pragma unroll
        for (int w = 0; w < NWORD; ++w) remv[w] = 0ULL;
        int nk = 0;
        for (int i = 0; i < M; ++i) {
            if (!((remv[i >> 6] >> (i & 63)) & 1ULL)) {
                if (nk < MAX_PER_CLASS) s_keep[nk] = i;
                nk++;
                const unsigned long long* mi = s_mask[i];
                #pragma unroll
                for (int w = 0; w < NWORD; ++w) remv[w] |= mi[w];
            }
        }
        s_nkeep = min(nk, MAX_PER_CLASS);
    }
    __syncthreads();

    // --- write per-class top-100 candidates ---
    int outbase = (b * NUM_CLASSES + c) * MAX_PER_CLASS;
    for (int k = tid; k < MAX_PER_CLASS; k += TPB) {
        if (k < s_nkeep) {
            int i = s_keep[k];
            g_cand_score[outbase + k] = s_score[i];
            g_cand_box[outbase + k]   = s_box[i];
        } else {
            g_cand_score[outbase + k] = -1.0f;
            g_cand_box[outbase + k]   = make_float4(0.f, 0.f, 0.f, 0.f);
        }
    }
}

__global__ void __launch_bounds__(TPB) topk_merge_kernel(float* __restrict__ out, int B) {
    const int b = blockIdx.x;
    const int tid = threadIdx.x;

    __shared__ float s_s[PAD2];
    __shared__ int   s_i[PAD2];
    __shared__ int   s_nv;

    for (int i = tid; i < PAD2; i += TPB) {
        if (i < NCAND) {
            s_s[i] = g_cand_score[b * NCAND + i];
            s_i[i] = i;
        } else {
            s_s[i] = -FLT_MAX;
            s_i[i] = 0x3fffffff;
        }
    }
    if (tid == 0) s_nv = 0;
    __syncthreads();

    // bitonic sort 2048: (score desc, idx asc) — matches top_k tie-breaking
    for (int k = 2; k <= PAD2; k <<= 1) {
        for (int j = k >> 1; j > 0; j >>= 1) {
            for (int i = tid; i < PAD2; i += TPB) {
                int ixj = i ^ j;
                if (ixj > i) {
                    float sa = s_s[i], sb = s_s[ixj];
                    int   ia = s_i[i], ib = s_i[ixj];
                    bool swapc = ((i & k) == 0) ? precedes(sb, ib, sa, ia)
                                                : precedes(sa, ia, sb, ib);
                    if (swapc) {
                        s_s[i] = sb; s_s[ixj] = sa;
                        s_i[i] = ib; s_i[ixj] = ia;
                    }
                }
            }
            __syncthreads();
        }
    }

    // emit top-100 rows: {x1,y1,x2,y2,cls,score}, zeros if score <= TH
    for (int k = tid; k < MAX_DET; k += TPB) {
        float sc = s_s[k];
        float* o = out + ((size_t)b * MAX_DET + k) * 6;
        if (sc > SCORE_TH) {
            int ci = s_i[k];
            float4 bx = g_cand_box[b * NCAND + ci];
            o[0] = bx.x; o[1] = bx.y; o[2] = bx.z; o[3] = bx.w;
            o[4] = (float)(ci / MAX_PER_CLASS);
            o[5] = sc;
            atomicAdd(&s_nv, 1);
        } else {
            o[0] = 0.f; o[1] = 0.f; o[2] = 0.f; o[3] = 0.f; o[4] = 0.f; o[5] = 0.f;
        }
    }
    __syncthreads();
    if (tid == 0) {
        // nvalid (int32 in reference) flattened into the float32 output buffer
        out[(size_t)B * MAX_DET * 6 + b] = (float)s_nv;
    }
}

extern "C" void kernel_launch(void* const* d_in, const int* in_sizes, int n_in,
                              void* d_out, int out_size) {
    const float* pred = (const float*)d_in[0];
    int B = in_sizes[0] / (N_BOX * 6);  // expected 4
    nms_per_class_kernel<<<B * NUM_CLASSES, TPB>>>(pred);
    topk_merge_kernel<<<B, TPB>>>((float*)d_out, B);
}

// round 2
// speedup vs baseline: 2.2737x; 2.2737x over previous
#include <cuda_runtime.h>
#include <cuda_bf16.h>
#include <float.h>

#define NUM_CLASSES 16
#define N_BOX 2048
#define MAXC 256            // max candidates per (image,class); observed ~122 +/- 11
#define NWORD 4             // MAXC/64 suppression-mask words
#define TPB 256
#define MAX_PER_CLASS 100
#define MAX_DET 100
#define NCAND (NUM_CLASSES * MAX_PER_CLASS)  // 1600
#define SCORE_TH 0.05f
#define IOU_TH 0.5f

// Scratch (B=4): per-class kept candidates as packed sort keys + boxes
//   key = (float_bits(score) << 32) | (0xFFFFFFFF - global_idx)
//   scores are > 0 so float bit pattern is order-preserving; ~idx gives
//   idx-ascending tie-break. Invalid slots: score bits = 0 (below any valid).
__device__ unsigned long long g_key[4 * NCAND];
__device__ float4             g_box[4 * NCAND];
__device__ int                g_cnt[4 * NUM_CLASSES];

__global__ void __launch_bounds__(TPB)
nms_class_kernel(const float* __restrict__ pred, float* __restrict__ out) {
    const int task = blockIdx.x;
    const int b = task >> 4;
    const int c = task & 15;
    const int tid = threadIdx.x;

    __shared__ unsigned long long s_key[MAXC];    // unsorted keys
    __shared__ unsigned long long s_skey[MAXC];   // rank-sorted keys
    __shared__ float4 s_box[MAXC];                // boxes in sorted order
    __shared__ unsigned long long s_mask[MAXC][NWORD];
    __shared__ int s_cnt, s_nkeep;
    __shared__ int s_keep[MAX_PER_CLASS];

    if (tid == 0) s_cnt = 0;
    // Pre-zero this image's output rows (redundant across the 16 class-blocks,
    // all write zeros -> benign; ordered before kernel 2 by the stream).
    for (int i = tid; i < MAX_DET * 6; i += TPB)
        out[(size_t)b * MAX_DET * 6 + i] = 0.f;
    __syncthreads();

    // ---- filter: class == c && score > TH ----
    const float* base = pred + (size_t)b * N_BOX * 6;
    const float fc = (float)c;
    for (int n = tid; n < N_BOX; n += TPB) {
        float cls = base[n * 6 + 4];
        float sc  = base[n * 6 + 5];
        if (cls == fc && sc > SCORE_TH) {
            int pos = atomicAdd(&s_cnt, 1);
            if (pos < MAXC)
                s_key[pos] = ((unsigned long long)__float_as_uint(sc) << 32)
                           | (unsigned long long)(0xFFFFFFFFu - (unsigned)n);
        }
    }
    __syncthreads();
    const int M = min(s_cnt, MAXC);

    // ---- rank sort: position = # keys greater (score desc, idx asc) ----
    for (int i = tid; i < M; i += TPB) {
        unsigned long long ki = s_key[i];
        int r = 0;
        #pragma unroll 4
        for (int j = 0; j < M; ++j) r += (s_key[j] > ki);
        s_skey[r] = ki;
    }
    __syncthreads();

    // ---- gather boxes in sorted order (original xyxy) ----
    for (int i = tid; i < M; i += TPB) {
        int n = (int)(0xFFFFFFFFu - (unsigned)(s_skey[i] & 0xFFFFFFFFull));
        const float* p = base + n * 6;
        s_box[i] = make_float4(p[0], p[1], p[2], p[3]);
    }
    __syncthreads();

    // ---- suppression bitmask: bit j of mask[i] iff j>i && IoU(i,j) > 0.5 ----
    const int NW = (M + 63) >> 6;
    for (int i = tid; i < M; i += TPB) {
        float4 bi = s_box[i];
        float areai = (bi.z - bi.x) * (bi.w - bi.y);
        for (int w = 0; w < NW; ++w) {
            unsigned long long bits = 0ULL;
            int j0 = w << 6;
            int jend = min(j0 + 64, M);
            for (int j = (j0 > i + 1 ? j0 : i + 1); j < jend; ++j) {
                float4 bj = s_box[j];
                float iw = fminf(bi.z, bj.z) - fmaxf(bi.x, bj.x);
                float ih = fminf(bi.w, bj.w) - fmaxf(bi.y, bj.y);
                iw = fmaxf(iw, 0.f);
                ih = fmaxf(ih, 0.f);
                float inter = iw * ih;
                if (inter > 0.f) {
                    float areaj = (bj.z - bj.x) * (bj.w - bj.y);
                    float uni = areai + areaj - inter;
                    if (inter / fmaxf(uni, 1e-8f) > IOU_TH)
                        bits |= 1ULL << (j - j0);
                }
            }
            s_mask[i][w] = bits;
        }
    }
    __syncthreads();

    // ---- greedy sweep (serial, ~M iterations of word ops) ----
    if (tid == 0) {
        unsigned long long remv[NWORD] = {0ULL, 0ULL, 0ULL, 0ULL};
        int nk = 0;
        for (int i = 0; i < M; ++i) {
            if (!((remv[i >> 6] >> (i & 63)) & 1ULL)) {
                if (nk < MAX_PER_CLASS) s_keep[nk] = i;
                nk++;
                const unsigned long long* mi = s_mask[i];
                #pragma unroll
                for (int w = 0; w < NWORD; ++w) remv[w] |= mi[w];
            }
        }
        int nkeep = min(nk, MAX_PER_CLASS);
        s_nkeep = nkeep;
        g_cnt[task] = nkeep;
    }
    __syncthreads();

    // ---- emit per-class kept list (keys re-tagged with global candidate id) ----
    const int nkeep = s_nkeep;
    for (int k = tid; k < MAX_PER_CLASS; k += TPB) {
        int gid = c * MAX_PER_CLASS + k;
        unsigned long long tag = (unsigned long long)(0xFFFFFFFFu - (unsigned)gid);
        if (k < nkeep) {
            int i = s_keep[k];
            g_key[b * NCAND + gid] = (s_skey[i] & 0xFFFFFFFF00000000ull) | tag;
            g_box[b * NCAND + gid] = s_box[i];
        } else {
            g_key[b * NCAND + gid] = tag;  // score bits 0 -> below all valid
        }
    }
}

__global__ void __launch_bounds__(128)
merge_topk_kernel(float* __restrict__ out, int B) {
    const int task = blockIdx.x;
    const int b = task >> 4;
    const int c = task & 15;
    const int tid = threadIdx.x;

    __shared__ unsigned long long s_key[NCAND];  // 12.8 KB
    for (int i = tid; i < NCAND; i += 128) s_key[i] = g_key[b * NCAND + i];
    __syncthreads();

    if (tid < MAX_PER_CLASS) {
        int gid = c * MAX_PER_CLASS + tid;
        unsigned long long myk = s_key[gid];
        float sc = __uint_as_float((unsigned)(myk >> 32));
        if (sc > SCORE_TH) {
            int r = 0;
            #pragma unroll 8
            for (int j = 0; j < NCAND; ++j) r += (s_key[j] > myk);
            if (r < MAX_DET) {
                float4 bx = g_box[b * NCAND + gid];
                float* o = out + ((size_t)b * MAX_DET + r) * 6;
                o[0] = bx.x; o[1] = bx.y; o[2] = bx.z; o[3] = bx.w;
                o[4] = (float)c;
                o[5] = sc;
            }
        }
    }

    // one block per image computes nvalid
    if (c == 0 && tid == 0) {
        int s = 0;
        #pragma unroll
        for (int i = 0; i < NUM_CLASSES; ++i) s += g_cnt[b * NUM_CLASSES + i];
        out[(size_t)B * MAX_DET * 6 + b] = (float)min(s, MAX_DET);
    }
}

extern "C" void kernel_launch(void* const* d_in, const int* in_sizes, int n_in,
                              void* d_out, int out_size) {
    const float* pred = (const float*)d_in[0];
    int B = in_sizes[0] / (N_BOX * 6);  // expected 4
    nms_class_kernel<<<B * NUM_CLASSES, TPB>>>(pred, (float*)d_out);
    merge_topk_kernel<<<B * NUM_CLASSES, 128>>>((float*)d_out, B);
}

// round 3
// speedup vs baseline: 2.8504x; 1.2537x over previous
#include <cuda_runtime.h>
#include <cuda_bf16.h>
#include <float.h>

#define NUM_CLASSES 16
#define N_BOX 2048
#define MAXC 256            // max candidates per (image,class); observed ~122 +/- 11
#define NWORD 4             // MAXC/64 suppression-mask words
#define TPB 256
#define MAX_PER_CLASS 100
#define MAX_DET 100
#define NCAND (NUM_CLASSES * MAX_PER_CLASS)  // 1600
#define SCORE_TH 0.05f
#define IOU_TH 0.5f

// Scratch (B=4): per-class kept candidates as packed sort keys + boxes.
//   key = (float_bits(score) << 32) | (0xFFFFFFFF - tag)
// Valid scores > 0 -> float bit pattern preserves order; ~tag breaks ties
// ascending. Each class's 100-slot list is STRICTLY DESCENDING (valid entries
// first by score/idx, then invalid tag-only entries, tags decreasing with k).
__device__ unsigned long long g_key[4 * NCAND];
__device__ float4             g_box[4 * NCAND];
__device__ int                g_cnt[4 * NUM_CLASSES];

__global__ void __launch_bounds__(TPB)
nms_class_kernel(const float* __restrict__ pred, float* __restrict__ out) {
    const int task = blockIdx.x;
    const int b = task >> 4;
    const int c = task & 15;
    const int tid = threadIdx.x;

    __shared__ unsigned long long s_key[MAXC];    // unsorted keys
    __shared__ unsigned long long s_skey[MAXC];   // rank-sorted keys
    __shared__ float4 s_box[MAXC];                // boxes in sorted order
    __shared__ unsigned long long s_mask[MAXC][NWORD];
    __shared__ int s_cnt, s_nkeep;
    __shared__ int s_keep[MAX_PER_CLASS];

    if (tid == 0) s_cnt = 0;
    // Zero this image's output rows once (only the c==0 block per image).
    // Stream-ordered before merge kernel, which scatter-writes valid rows.
    if (c == 0) {
        for (int i = tid; i < MAX_DET * 6; i += TPB)
            out[(size_t)b * MAX_DET * 6 + i] = 0.f;
    }
    __syncthreads();

    // ---- filter: class == c && score > TH  (cls,score as one float2) ----
    const float* base = pred + (size_t)b * N_BOX * 6;
    const float2* cs = (const float2*)base;       // (cls,score) at index 3n+2
    const float fc = (float)c;
    for (int n = tid; n < N_BOX; n += TPB) {
        float2 v = cs[3 * n + 2];
        if (v.x == fc && v.y > SCORE_TH) {
            int pos = atomicAdd(&s_cnt, 1);
            if (pos < MAXC)
                s_key[pos] = ((unsigned long long)__float_as_uint(v.y) << 32)
                           | (unsigned long long)(0xFFFFFFFFu - (unsigned)n);
        }
    }
    __syncthreads();
    const int M = min(s_cnt, MAXC);

    // ---- rank sort: position = # keys greater (score desc, idx asc) ----
    for (int i = tid; i < M; i += TPB) {
        unsigned long long ki = s_key[i];
        int r = 0;
        #pragma unroll 4
        for (int j = 0; j < M; ++j) r += (s_key[j] > ki);
        s_skey[r] = ki;
    }
    __syncthreads();

    // ---- gather boxes in sorted order (original xyxy) ----
    for (int i = tid; i < M; i += TPB) {
        int n = (int)(0xFFFFFFFFu - (unsigned)(s_skey[i] & 0xFFFFFFFFull));
        const float2* p = (const float2*)(base + n * 6);
        float2 p0 = p[0], p1 = p[1];
        s_box[i] = make_float4(p0.x, p0.y, p1.x, p1.y);
    }
    __syncthreads();

    // ---- suppression bitmask over (i, word) pairs ----
    const int NW = (M + 63) >> 6;
    for (int item = tid; item < M * NW; item += TPB) {
        const int i = item / NW;
        const int w = item - i * NW;
        float4 bi = s_box[i];
        float areai = (bi.z - bi.x) * (bi.w - bi.y);
        unsigned long long bits = 0ULL;
        int j0 = w << 6;
        int jend = min(j0 + 64, M);
        for (int j = (j0 > i + 1 ? j0 : i + 1); j < jend; ++j) {
            float4 bj = s_box[j];
            float iw = fminf(bi.z, bj.z) - fmaxf(bi.x, bj.x);
            float ih = fminf(bi.w, bj.w) - fmaxf(bi.y, bj.y);
            iw = fmaxf(iw, 0.f);
            ih = fmaxf(ih, 0.f);
            float inter = iw * ih;
            if (inter > 0.f) {
                float areaj = (bj.z - bj.x) * (bj.w - bj.y);
                float uni = areai + areaj - inter;
                if (inter / fmaxf(uni, 1e-8f) > IOU_TH)
                    bits |= 1ULL << (j - j0);
            }
        }
        s_mask[i][w] = bits;
    }
    __syncthreads();

    // ---- greedy sweep (serial, ~M iterations of word ops) ----
    if (tid == 0) {
        unsigned long long remv[NWORD] = {0ULL, 0ULL, 0ULL, 0ULL};
        int nk = 0;
        for (int i = 0; i < M; ++i) {
            if (!((remv[i >> 6] >> (i & 63)) & 1ULL)) {
                if (nk < MAX_PER_CLASS) s_keep[nk] = i;
                nk++;
                const unsigned long long* mi = s_mask[i];
                #pragma unroll
                for (int w = 0; w < NWORD; ++w) remv[w] |= mi[w];
            }
        }
        int nkeep = min(nk, MAX_PER_CLASS);
        s_nkeep = nkeep;
        g_cnt[task] = nkeep;
    }
    __syncthreads();

    // ---- emit per-class kept list, strictly descending in k ----
    const int nkeep = s_nkeep;
    for (int k = tid; k < MAX_PER_CLASS; k += TPB) {
        int gid = c * MAX_PER_CLASS + k;
        unsigned long long tag = (unsigned long long)(0xFFFFFFFFu - (unsigned)gid);
        if (k < nkeep) {
            int i = s_keep[k];
            g_key[b * NCAND + gid] = (s_skey[i] & 0xFFFFFFFF00000000ull) | tag;
            g_box[b * NCAND + gid] = s_box[i];
        } else {
            g_key[b * NCAND + gid] = tag;  // score bits 0 -> below all valid
        }
    }
}

__global__ void __launch_bounds__(128)
merge_topk_kernel(float* __restrict__ out, int B) {
    const int task = blockIdx.x;
    const int b = task >> 4;
    const int c = task & 15;
    const int tid = threadIdx.x;

    __shared__ unsigned long long s_key[NCAND];  // 12.8 KB
    for (int i = tid; i < NCAND; i += 128) s_key[i] = g_key[b * NCAND + i];
    __syncthreads();

    if (tid < MAX_PER_CLASS) {
        const int gid = c * MAX_PER_CLASS + tid;
        const unsigned long long myk = s_key[gid];
        const float sc = __uint_as_float((unsigned)(myk >> 32));
        if (sc > SCORE_TH) {
            // Own class contributes exactly `tid` greater elements (list is
            // strictly descending and contains myk at position tid).
            int rank = tid;
            // 15 independent binary searches (depth 7 each) -> high ILP.
            #pragma unroll
            for (int cc = 0; cc < NUM_CLASSES; ++cc) {
                if (cc == c) continue;
                const unsigned long long* arr = s_key + cc * MAX_PER_CLASS;
                int lo = 0, len = MAX_PER_CLASS;
                while (len > 0) {
                    int half = len >> 1;
                    if (arr[lo + half] > myk) { lo += half + 1; len -= half + 1; }
                    else                      { len = half; }
                }
                rank += lo;   // count of elements > myk in class cc
            }
            if (rank < MAX_DET) {
                float4 bx = g_box[b * NCAND + gid];
                float* o = out + ((size_t)b * MAX_DET + rank) * 6;
                o[0] = bx.x; o[1] = bx.y; o[2] = bx.z; o[3] = bx.w;
                o[4] = (float)c;
                o[5] = sc;
            }
        }
    }

    // one block per image computes nvalid
    if (c == 0 && tid == 0) {
        int s = 0;
        #pragma unroll
        for (int i = 0; i < NUM_CLASSES; ++i) s += g_cnt[b * NUM_CLASSES + i];
        out[(size_t)B * MAX_DET * 6 + b] = (float)min(s, MAX_DET);
    }
}

extern "C" void kernel_launch(void* const* d_in, const int* in_sizes, int n_in,
                              void* d_out, int out_size) {
    const float* pred = (const float*)d_in[0];
    int B = in_sizes[0] / (N_BOX * 6);  // expected 4
    nms_class_kernel<<<B * NUM_CLASSES, TPB>>>(pred, (float*)d_out);
    merge_topk_kernel<<<B * NUM_CLASSES, 128>>>((float*)d_out, B);
}

// round 5
// speedup vs baseline: 3.1757x; 1.1141x over previous
#include <cuda_runtime.h>
#include <cuda_bf16.h>
#include <float.h>

#define NUM_CLASSES 16
#define N_BOX 2048
#define MAXC 256            // max candidates per (image,class); observed ~122 +/- 11
#define NWORD 4             // MAXC/64 suppression-mask words
#define TPB 256
#define MAX_PER_CLASS 100
#define MAX_DET 100
#define NCAND (NUM_CLASSES * MAX_PER_CLASS)  // 1600
#define SCORE_TH 0.05f
#define IOU_TH 0.5f

// Scratch (B=4): per-class kept candidates as packed sort keys + boxes.
//   key = (float_bits(score) << 32) | (0xFFFFFFFF - tag)
// Valid scores > 0 -> float bit pattern preserves order; ~tag breaks ties
// ascending. Each class's 100-slot list is STRICTLY DESCENDING.
__device__ unsigned long long g_key[4 * NCAND];
__device__ float4             g_box[4 * NCAND];
__device__ int                g_cnt[4 * NUM_CLASSES];

// Grid barrier state (replay-safe: count returns to 0 every launch, gen is
// monotone across launches).
__device__ unsigned g_bar_count = 0;
__device__ unsigned g_bar_gen   = 0;

__global__ void __launch_bounds__(TPB)
nms_fused_kernel(const float* __restrict__ pred, float* __restrict__ out, int B) {
    const int task = blockIdx.x;
    const int b = task >> 4;
    const int c = task & 15;
    const int tid = threadIdx.x;

    __shared__ union {
        struct {
            unsigned long long key[MAXC];          // unsorted keys
            unsigned long long skey[MAXC];         // rank-sorted keys
            float4             box[MAXC];          // boxes in sorted order
            unsigned long long mask[MAXC][NWORD];  // suppression bitmask
        } a;                                       // 16.4 KB (phase A)
        unsigned long long merge_key[NCAND];       // 12.8 KB (phase B)
    } s;
    __shared__ int s_cnt, s_nkeep;
    __shared__ int s_keep[MAX_PER_CLASS];

    if (tid == 0) s_cnt = 0;
    // Zero this image's output rows (one block per image). Ordered before the
    // phase-B scatter writes by the grid barrier.
    if (c == 0) {
        for (int i = tid; i < MAX_DET * 6; i += TPB)
            out[(size_t)b * MAX_DET * 6 + i] = 0.f;
    }
    __syncthreads();

    // ================= PHASE A: per-(image,class) NMS =================

    // ---- filter: class == c && score > TH (cls,score as one float2) ----
    const float* base = pred + (size_t)b * N_BOX * 6;
    const float2* cs = (const float2*)base;       // (cls,score) at float2 idx 3n+2
    const float fc = (float)c;
    for (int n = tid; n < N_BOX; n += TPB) {
        float2 v = cs[3 * n + 2];
        if (v.x == fc && v.y > SCORE_TH) {
            int pos = atomicAdd(&s_cnt, 1);
            if (pos < MAXC)
                s.a.key[pos] = ((unsigned long long)__float_as_uint(v.y) << 32)
                             | (unsigned long long)(0xFFFFFFFFu - (unsigned)n);
        }
    }
    __syncthreads();
    const int M = min(s_cnt, MAXC);

    // ---- rank sort: position = # keys greater (score desc, idx asc) ----
    for (int i = tid; i < M; i += TPB) {
        unsigned long long ki = s.a.key[i];
        int r = 0;
        #pragma unroll 4
        for (int j = 0; j < M; ++j) r += (s.a.key[j] > ki);
        s.a.skey[r] = ki;
    }
    __syncthreads();

    // ---- gather boxes in sorted order (original xyxy) ----
    for (int i = tid; i < M; i += TPB) {
        int n = (int)(0xFFFFFFFFu - (unsigned)(s.a.skey[i] & 0xFFFFFFFFull));
        const float2* p = (const float2*)(base + n * 6);
        float2 p0 = p[0], p1 = p[1];
        s.a.box[i] = make_float4(p0.x, p0.y, p1.x, p1.y);
    }
    __syncthreads();

    // ---- suppression bitmask over (i, word) pairs ----
    const int NW = (M + 63) >> 6;
    for (int item = tid; item < M * NW; item += TPB) {
        const int i = item / NW;
        const int w = item - i * NW;
        float4 bi = s.a.box[i];
        float areai = (bi.z - bi.x) * (bi.w - bi.y);
        unsigned long long bits = 0ULL;
        int j0 = w << 6;
        int jend = min(j0 + 64, M);
        for (int j = (j0 > i + 1 ? j0 : i + 1); j < jend; ++j) {
            float4 bj = s.a.box[j];
            float iw = fminf(bi.z, bj.z) - fmaxf(bi.x, bj.x);
            float ih = fminf(bi.w, bj.w) - fmaxf(bi.y, bj.y);
            iw = fmaxf(iw, 0.f);
            ih = fmaxf(ih, 0.f);
            float inter = iw * ih;
            if (inter > 0.f) {
                float areaj = (bj.z - bj.x) * (bj.w - bj.y);
                float uni = areai + areaj - inter;
                if (inter / fmaxf(uni, 1e-8f) > IOU_TH)
                    bits |= 1ULL << (j - j0);
            }
        }
        s.a.mask[i][w] = bits;
    }
    __syncthreads();

    // ---- greedy sweep: serial, but mask-row loads hoisted (pipelineable) ----
    if (tid == 0) {
        unsigned long long remv0 = 0, remv1 = 0, remv2 = 0, remv3 = 0;
        int nk = 0;
        for (int i = 0; i < M; ++i) {
            // Unconditional loads: address independent of keep decision, so
            // LDS latency overlaps the remv dependency chain. Words >= NW may
            // be garbage but only pollute remv bits >= M, which are never read.
            unsigned long long m0 = s.a.mask[i][0];
            unsigned long long m1 = s.a.mask[i][1];
            unsigned long long m2 = s.a.mask[i][2];
            unsigned long long m3 = s.a.mask[i][3];
            unsigned long long rw = (i < 64) ? remv0 : (i < 128) ? remv1
                                  : (i < 192) ? remv2 : remv3;
            if (!((rw >> (i & 63)) & 1ULL)) {
                if (nk < MAX_PER_CLASS) s_keep[nk] = i;
                nk++;
                remv0 |= m0; remv1 |= m1; remv2 |= m2; remv3 |= m3;
            }
        }
        int nkeep = min(nk, MAX_PER_CLASS);
        s_nkeep = nkeep;
        g_cnt[task] = nkeep;
    }
    __syncthreads();

    // ---- emit per-class kept list, strictly descending in k ----
    const int nkeep = s_nkeep;
    for (int k = tid; k < MAX_PER_CLASS; k += TPB) {
        int gid = c * MAX_PER_CLASS + k;
        unsigned long long tag = (unsigned long long)(0xFFFFFFFFu - (unsigned)gid);
        if (k < nkeep) {
            int i = s_keep[k];
            g_key[b * NCAND + gid] = (s.a.skey[i] & 0xFFFFFFFF00000000ull) | tag;
            g_box[b * NCAND + gid] = s.a.box[i];
        } else {
            g_key[b * NCAND + gid] = tag;  // score bits 0 -> below all valid
        }
    }

    // ================= GRID BARRIER (64 co-resident blocks) =================
    // 64 blocks x 256 thr x ~16.5KB smem: all blocks resident simultaneously
    // on 148 SMs, so a spin barrier cannot deadlock.
    __threadfence();      // make this block's g_key/g_box/g_cnt writes visible
    __syncthreads();
    if (tid == 0) {
        volatile unsigned* vgen = &g_bar_gen;
        unsigned my_gen = *vgen;          // read before arriving: safe, gen can
                                          // only bump after ALL 64 arrive
        unsigned ticket = atomicAdd(&g_bar_count, 1);
        if (ticket == gridDim.x - 1) {
            atomicExch(&g_bar_count, 0);  // reset for next graph replay
            __threadfence();
            atomicAdd(&g_bar_gen, 1);     // release
        } else {
            while (*vgen == my_gen) { __nanosleep(64); }
        }
    }
    __syncthreads();

    // ================= PHASE B: global top-100 merge =================
    // Reuse shared as the image's 1600-key table. __ldcg: read via L2,
    // bypassing any stale L1 lines from before the barrier.
    for (int i = tid; i < NCAND; i += TPB)
        s.merge_key[i] = __ldcg(&g_key[b * NCAND + i]);
    __syncthreads();

    if (tid < MAX_PER_CLASS) {
        const int gid = c * MAX_PER_CLASS + tid;
        const unsigned long long myk = s.merge_key[gid];
        const float sc = __uint_as_float((unsigned)(myk >> 32));
        if (sc > SCORE_TH) {
            // Own class contributes exactly `tid` greater elements.
            int rank = tid;
            // 15 independent binary searches (depth 7) -> high ILP.
            #pragma unroll
            for (int cc = 0; cc < NUM_CLASSES; ++cc) {
                if (cc == c) continue;
                const unsigned long long* arr = s.merge_key + cc * MAX_PER_CLASS;
                int lo = 0, len = MAX_PER_CLASS;
                while (len > 0) {
                    int half = len >> 1;
                    if (arr[lo + half] > myk) { lo += half + 1; len -= half + 1; }
                    else                      { len = half; }
                }
                rank += lo;   // count of elements > myk in class cc
            }
            if (rank < MAX_DET) {
                float4 bx = __ldcg(&g_box[b * NCAND + gid]);
                float* o = out + ((size_t)b * MAX_DET + rank) * 6;
                o[0] = bx.x; o[1] = bx.y; o[2] = bx.z; o[3] = bx.w;
                o[4] = (float)c;
                o[5] = sc;
            }
        }
    }

    // one block per image computes nvalid
    if (c == 0 && tid == 0) {
        int sum = 0;
        #pragma unroll
        for (int i = 0; i < NUM_CLASSES; ++i) sum += __ldcg(&g_cnt[b * NUM_CLASSES + i]);
        out[(size_t)B * MAX_DET * 6 + b] = (float)min(sum, MAX_DET);
    }
}

extern "C" void kernel_launch(void* const* d_in, const int* in_sizes, int n_in,
                              void* d_out, int out_size) {
    const float* pred = (const float*)d_in[0];
    int B = in_sizes[0] / (N_BOX * 6);  // expected 4
    nms_fused_kernel<<<B * NUM_CLASSES, TPB>>>(pred, (float*)d_out, B);
}